// round 6
// baseline (speedup 1.0000x reference)
#include <cuda_runtime.h>
#include <cstdint>

#define WIN_N   49
#define DIMC    384
#define NHEAD   12
#define HD      32
#define BWIN    4096
#define MROWS   (BWIN * WIN_N)      /* 200704 */
#define QKV_N   (3 * DIMC)          /* 1152   */

#define QK_SCALE 0.17677669529663687f   /* 32^-0.5 */

/* -------- scratch: static device globals (allocation-free per harness rules) -------- */
__device__ __align__(256) float g_qkv[(size_t)MROWS * QKV_N];  /* [m][1152]: q|k|v, q pre-scaled */
__device__ __align__(256) float g_ctx[(size_t)MROWS * DIMC];   /* attention output [b][n][h*32+d] */

/* -------- packed fp32x2 helpers (sm_103a) -------- */
__device__ __forceinline__ unsigned long long pack2(float x, float y) {
    unsigned long long r;
    asm("mov.b64 %0, {%1, %2};" : "=l"(r) : "r"(__float_as_uint(x)), "r"(__float_as_uint(y)));
    return r;
}
__device__ __forceinline__ void unpack2(unsigned long long p, float &x, float &y) {
    unsigned int lo, hi;
    asm("mov.b64 {%0, %1}, %2;" : "=r"(lo), "=r"(hi) : "l"(p));
    x = __uint_as_float(lo); y = __uint_as_float(hi);
}
__device__ __forceinline__ void fma2(unsigned long long &acc, unsigned long long a, unsigned long long b) {
    asm("fma.rn.f32x2 %0, %1, %2, %0;" : "+l"(acc) : "l"(a), "l"(b));
}

/* ============================================================================
 * C[M x N] = A[M x K] * W[N x K]^T + bias[N]   (row-major everywhere)
 * 128x128x16 tile, 256 threads, 8x8 per thread in split 4+4 layout,
 * accumulation via packed fma.rn.f32x2 (two independent rn-FMAs -> fp32-exact).
 * SCALE_Q: multiply columns < 384 (the q block) by 32^-0.5 after bias add.
 * M, N, K are exact multiples of the tile sizes here -> no bounds checks.
 * Shared tiles are __align__(16): we issue LDS.128 / 16-byte casts on them.
 * ==========================================================================*/
template<int N, bool SCALE_Q>
__global__ void __launch_bounds__(256, 2)
gemm_xwT(const float* __restrict__ A, const float* __restrict__ W,
         const float* __restrict__ bias, float* __restrict__ C, int K)
{
    constexpr int BM = 128, BN = 128, BK = 16;
    __shared__ __align__(16) float As[BK][BM];
    __shared__ __align__(16) float Bs[BK][BN];

    const int tid = threadIdx.x;
    const int m0 = blockIdx.y * BM;
    const int n0 = blockIdx.x * BN;
    const int ty = tid >> 4, tx = tid & 15;
    const int row0 = ty * 4, row1 = row0 + 64;
    const int col0 = tx * 4, col1 = col0 + 64;

    unsigned long long acc[8][4];
    #pragma unroll
    for (int i = 0; i < 8; i++)
        #pragma unroll
        for (int p = 0; p < 4; p++) acc[i][p] = 0ULL;  /* (0.f, 0.f) */

    const int lr = tid >> 2;          /* 0..63 */
    const int lc = (tid & 3) * 4;     /* 0,4,8,12 */

    for (int k0 = 0; k0 < K; k0 += BK) {
        #pragma unroll
        for (int rep = 0; rep < 2; rep++) {
            const int r = lr + rep * 64;
            float4 av = *reinterpret_cast<const float4*>(&A[(size_t)(m0 + r) * K + k0 + lc]);
            As[lc + 0][r] = av.x; As[lc + 1][r] = av.y;
            As[lc + 2][r] = av.z; As[lc + 3][r] = av.w;
            float4 bv = *reinterpret_cast<const float4*>(&W[(size_t)(n0 + r) * K + k0 + lc]);
            Bs[lc + 0][r] = bv.x; Bs[lc + 1][r] = bv.y;
            Bs[lc + 2][r] = bv.z; Bs[lc + 3][r] = bv.w;
        }
        __syncthreads();

        #pragma unroll
        for (int kk = 0; kk < BK; kk++) {
            float4 a0 = *reinterpret_cast<const float4*>(&As[kk][row0]);
            float4 a1 = *reinterpret_cast<const float4*>(&As[kk][row1]);
            ulonglong2 b01 = *reinterpret_cast<const ulonglong2*>(&Bs[kk][col0]);
            ulonglong2 b23 = *reinterpret_cast<const ulonglong2*>(&Bs[kk][col1]);
            const unsigned long long bb0 = b01.x, bb1 = b01.y, bb2 = b23.x, bb3 = b23.y;
            float av[8] = {a0.x, a0.y, a0.z, a0.w, a1.x, a1.y, a1.z, a1.w};
            #pragma unroll
            for (int i = 0; i < 8; i++) {
                unsigned long long ap = pack2(av[i], av[i]);
                fma2(acc[i][0], ap, bb0);
                fma2(acc[i][1], ap, bb1);
                fma2(acc[i][2], ap, bb2);
                fma2(acc[i][3], ap, bb3);
            }
        }
        __syncthreads();
    }

    const bool do_scale = SCALE_Q && (n0 < DIMC);  /* uniform per block: BN=128 <= 384 */
    #pragma unroll
    for (int i = 0; i < 8; i++) {
        const int r = (i < 4) ? (row0 + i) : (row1 + i - 4);
        float* crow = C + (size_t)(m0 + r) * N + n0;
        #pragma unroll
        for (int p = 0; p < 4; p++) {
            const int cb = ((p < 2) ? col0 : col1) + (p & 1) * 2;
            float x, y;
            unpack2(acc[i][p], x, y);
            x += bias[n0 + cb];
            y += bias[n0 + cb + 1];
            if (do_scale) { x *= QK_SCALE; y *= QK_SCALE; }
            *reinterpret_cast<float2*>(&crow[cb]) = make_float2(x, y);
        }
    }
}

/* ============================================================================
 * Windowed attention: one block per (window b, head h).
 * smem: q/k/v [49 x 32] (padded strides), logits buffer seeded with the
 * gathered relative-position bias. 4x4 register tiles for QK^T and PV to
 * stay off the smem-crossbar byte limit. vs is __align__(16) for LDS.128.
 * ==========================================================================*/
#define QS 33   /* q/k row stride (odd -> conflict-free scalar access) */
#define VS 36   /* v row stride   (mult of 4 -> aligned float4 access) */

__global__ void __launch_bounds__(128)
win_attn(const float* __restrict__ bias_table, const int* __restrict__ rel_index)
{
    __shared__ __align__(16) float qs[WIN_N * QS];
    __shared__ __align__(16) float ks[WIN_N * QS];
    __shared__ __align__(16) float vs[WIN_N * VS];
    __shared__ __align__(16) float ls[WIN_N * WIN_N];

    const int h = blockIdx.x;
    const int b = blockIdx.y;
    const int tid = threadIdx.x;

    /* load q/k/v rows for this (b,h) */
    const float* base = g_qkv + (size_t)b * WIN_N * QKV_N + h * HD;
    for (int idx = tid; idx < WIN_N * HD; idx += 128) {
        const int n = idx >> 5, d = idx & 31;
        const float* p = base + (size_t)n * QKV_N + d;
        qs[n * QS + d] = p[0];          /* already scaled by 32^-0.5 */
        ks[n * QS + d] = p[DIMC];
        vs[n * VS + d] = p[2 * DIMC];
    }
    /* seed logits with gathered relative-position bias */
    for (int idx = tid; idx < WIN_N * WIN_N; idx += 128)
        ls[idx] = bias_table[rel_index[idx] * NHEAD + h];
    __syncthreads();

    /* logits += q . k  (4x4 tiles over the 49x49 grid; 13x13 = 169 tiles) */
    for (int t = tid; t < 169; t += 128) {
        const int tn = t / 13, tm = t - tn * 13;
        const int nb = tn * 4, mb = tm * 4;
        const float* qp[4]; const float* kp[4];
        #pragma unroll
        for (int i = 0; i < 4; i++) {
            qp[i] = &qs[min(nb + i, WIN_N - 1) * QS];
            kp[i] = &ks[min(mb + i, WIN_N - 1) * QS];
        }
        float a[4][4] = {};
        #pragma unroll
        for (int d = 0; d < HD; d++) {
            float qv[4], kv[4];
            #pragma unroll
            for (int i = 0; i < 4; i++) qv[i] = qp[i][d];
            #pragma unroll
            for (int j = 0; j < 4; j++) kv[j] = kp[j][d];
            #pragma unroll
            for (int i = 0; i < 4; i++)
                #pragma unroll
                for (int j = 0; j < 4; j++) a[i][j] += qv[i] * kv[j];
        }
        #pragma unroll
        for (int i = 0; i < 4; i++) {
            if (nb + i >= WIN_N) break;
            #pragma unroll
            for (int j = 0; j < 4; j++)
                if (mb + j < WIN_N) ls[(nb + i) * WIN_N + mb + j] += a[i][j];
        }
    }
    __syncthreads();

    /* softmax per row: 4 warps stride the 49 rows; 32 lanes cover 49 cols */
    {
        const int warp = tid >> 5, lane = tid & 31;
        for (int n = warp; n < WIN_N; n += 4) {
            float* row = &ls[n * WIN_N];
            const bool has1 = (lane + 32) < WIN_N;
            float v0 = row[lane];
            float v1 = has1 ? row[lane + 32] : -3.402823e38f;
            float mx = fmaxf(v0, v1);
            #pragma unroll
            for (int off = 16; off >= 1; off >>= 1)
                mx = fmaxf(mx, __shfl_xor_sync(0xffffffffu, mx, off));
            float e0 = __expf(v0 - mx);
            float e1 = has1 ? __expf(v1 - mx) : 0.f;
            float s = e0 + e1;
            #pragma unroll
            for (int off = 16; off >= 1; off >>= 1)
                s += __shfl_xor_sync(0xffffffffu, s, off);
            const float inv = 1.f / s;
            row[lane] = e0 * inv;
            if (has1) row[lane + 32] = e1 * inv;
        }
    }
    __syncthreads();

    /* ctx = P @ V  (4 rows x 4 dims per thread: 13 x 8 = 104 tiles) */
    float* ctx = g_ctx + (size_t)b * WIN_N * DIMC + h * HD;
    for (int t = tid; t < 13 * 8; t += 128) {
        const int tn = t >> 3, td = t & 7;
        const int nb = tn * 4, d0 = td * 4;
        const float* pr[4];
        #pragma unroll
        for (int i = 0; i < 4; i++) pr[i] = &ls[min(nb + i, WIN_N - 1) * WIN_N];
        float a[4][4] = {};
        for (int m = 0; m < WIN_N; m++) {
            float4 vv = *reinterpret_cast<const float4*>(&vs[m * VS + d0]);
            float pv[4];
            #pragma unroll
            for (int i = 0; i < 4; i++) pv[i] = pr[i][m];
            #pragma unroll
            for (int i = 0; i < 4; i++) {
                a[i][0] += pv[i] * vv.x; a[i][1] += pv[i] * vv.y;
                a[i][2] += pv[i] * vv.z; a[i][3] += pv[i] * vv.w;
            }
        }
        #pragma unroll
        for (int i = 0; i < 4; i++) {
            if (nb + i >= WIN_N) break;
            float* o = ctx + (size_t)(nb + i) * DIMC + d0;
            o[0] = a[i][0]; o[1] = a[i][1]; o[2] = a[i][2]; o[3] = a[i][3];
        }
    }
}

/* ============================================================================ */
extern "C" void kernel_launch(void* const* d_in, const int* in_sizes, int n_in,
                              void* d_out, int out_size)
{
    const float* x          = (const float*)d_in[0];
    const float* qkv_w      = (const float*)d_in[1];
    const float* qkv_b      = (const float*)d_in[2];
    const float* proj_w     = (const float*)d_in[3];
    const float* proj_b     = (const float*)d_in[4];
    const float* bias_table = (const float*)d_in[5];
    const int*   rel_index  = (const int*)d_in[6];
    float*       out        = (float*)d_out;

    float *qkv_ptr = nullptr, *ctx_ptr = nullptr;
    cudaGetSymbolAddress((void**)&qkv_ptr, g_qkv);
    cudaGetSymbolAddress((void**)&ctx_ptr, g_ctx);

    /* 1) QKV = X * Wqkv^T + b, q part pre-scaled by 32^-0.5 */
    dim3 g1(QKV_N / 128, MROWS / 128);   /* (9, 1568) */
    gemm_xwT<QKV_N, true><<<g1, 256>>>(x, qkv_w, qkv_b, qkv_ptr, DIMC);

    /* 2) windowed attention with relative-position bias */
    dim3 g2(NHEAD, BWIN);                /* (12, 4096) */
    win_attn<<<g2, 128>>>(bias_table, rel_index);

    /* 3) OUT = CTX * Wproj^T + b */
    dim3 g3(DIMC / 128, MROWS / 128);    /* (3, 1568) */
    gemm_xwT<DIMC, false><<<g3, 256>>>(ctx_ptr, proj_w, proj_b, out, DIMC);
}

// round 10
// speedup vs baseline: 2.2486x; 2.2486x over previous
#include <cuda_runtime.h>
#include <cstdint>

#define WIN_N   49
#define DIMC    384
#define NHEAD   12
#define HD      32
#define BWIN    4096
#define MROWS   (BWIN * WIN_N)      /* 200704 */
#define QKV_N   (3 * DIMC)          /* 1152   */

#define QK_SCALE 0.17677669529663687f   /* 32^-0.5 */

#define BK      32                  /* K per pipeline chunk */
#define NCHUNK  (DIMC / BK)         /* 12 */
#define SPAD    36                  /* smem row stride in floats (conflict-free frags) */
#define STAGE_FLOATS (2 * 128 * SPAD)          /* A tile + B tile per stage = 9216 */
#define SMEM_DYN (2 * STAGE_FLOATS * 4)        /* 73728 B, double buffered */

/* -------- scratch: static device globals (allocation-free per harness rules) -------- */
__device__ __align__(256) float g_qkv[(size_t)MROWS * QKV_N];   /* fp32 q|k|v (q pre-scaled) */
__device__ __align__(256) float g_ctx[(size_t)MROWS * DIMC];    /* attention out, tf32-rounded */
__device__ __align__(256) float g_bias[NHEAD * WIN_N * WIN_N];  /* gathered rel-pos bias */
__device__ __align__(256) float g_xt [(size_t)MROWS * DIMC];    /* x,  tf32-rounded */
__device__ __align__(256) float g_wqt[QKV_N * DIMC];            /* qkv_w, tf32-rounded */
__device__ __align__(256) float g_wpt[DIMC * DIMC];             /* proj_w, tf32-rounded */

/* ======================= helpers (all plain sm_80+ PTX) ======================= */
__device__ __forceinline__ uint32_t f2tf32(float x) {
    uint32_t r; asm("cvt.rna.tf32.f32 %0, %1;" : "=r"(r) : "f"(x)); return r;
}
__device__ __forceinline__ float tf32r(float x) { return __uint_as_float(f2tf32(x)); }

__device__ __forceinline__ void cp16(float* dst_smem, const float* src_gmem) {
    uint32_t d = (uint32_t)__cvta_generic_to_shared(dst_smem);
    asm volatile("cp.async.cg.shared.global [%0], [%1], 16;" :: "r"(d), "l"(src_gmem) : "memory");
}
__device__ __forceinline__ void cp_commit() {
    asm volatile("cp.async.commit_group;" ::: "memory");
}
__device__ __forceinline__ void cp_wait0() {
    asm volatile("cp.async.wait_group 0;" ::: "memory");
}

/* ============================================================================
 * Tensor-core GEMM via portable mma.sync (tf32, fp32 accum):
 *   C[M x N] = A[M x 384] * W[N x 384]^T + bias[N]
 * A and W must already be tf32-rounded fp32 (cvt.rna done ahead of time) so
 * cp.async can stage raw bytes. 128x128 CTA tile, 4 warps, 64x64 warp tile.
 * Smem rows padded to 36 floats: fragment-load banks = (4*grp + sub) mod 32,
 * all 32 distinct -> conflict-free LDS.
 * ==========================================================================*/
template<int N, bool SCALE_Q>
__global__ void __launch_bounds__(128)
gemm_mma(const float* __restrict__ A, const float* __restrict__ W,
         const float* __restrict__ bias, float* __restrict__ C)
{
    extern __shared__ __align__(16) float dsm[];
    const int tid  = threadIdx.x;
    const int m0   = blockIdx.y * 128;
    const int n0   = blockIdx.x * 128;
    const int wid  = tid >> 5, lane = tid & 31;
    const int wm   = wid >> 1, wn = wid & 1;        /* warp grid 2x2 */
    const int grp  = lane >> 2, sub = lane & 3;

    float acc[4][8][4];
    #pragma unroll
    for (int mt = 0; mt < 4; mt++)
        #pragma unroll
        for (int nt = 0; nt < 8; nt++)
            #pragma unroll
            for (int r = 0; r < 4; r++) acc[mt][nt][r] = 0.f;

    /* ---- prefetch chunk kc into buffer buf ---- */
    auto prefetch = [&](int kc, int buf) {
        float* As = dsm + buf * STAGE_FLOATS;
        float* Bs = As + 128 * SPAD;
        const int k0 = kc * BK;
        #pragma unroll
        for (int i = 0; i < 8; i++) {
            const int idx = tid + i * 128;          /* 0..1023 */
            const int r = idx >> 3, q = idx & 7;    /* row, float4-slot */
            cp16(As + r * SPAD + q * 4, A + (size_t)(m0 + r) * DIMC + k0 + q * 4);
            cp16(Bs + r * SPAD + q * 4, W + (size_t)(n0 + r) * DIMC + k0 + q * 4);
        }
        cp_commit();
    };

    prefetch(0, 0);

    for (int kc = 0; kc < NCHUNK; kc++) {
        cp_wait0();
        __syncthreads();
        if (kc + 1 < NCHUNK) prefetch(kc + 1, (kc + 1) & 1);

        const uint32_t* As = (const uint32_t*)(dsm + (kc & 1) * STAGE_FLOATS);
        const uint32_t* Bs = As + 128 * SPAD;

        #pragma unroll
        for (int ks = 0; ks < 4; ks++) {
            const int k0 = ks * 8;
            uint32_t a[4][4];
            #pragma unroll
            for (int mt = 0; mt < 4; mt++) {
                const uint32_t* p = As + (wm * 64 + mt * 16 + grp) * SPAD + k0 + sub;
                a[mt][0] = p[0];
                a[mt][1] = p[8 * SPAD];
                a[mt][2] = p[4];
                a[mt][3] = p[8 * SPAD + 4];
            }
            #pragma unroll
            for (int nt = 0; nt < 8; nt++) {
                const uint32_t* p = Bs + (wn * 64 + nt * 8 + grp) * SPAD + k0 + sub;
                const uint32_t b0 = p[0], b1 = p[4];
                #pragma unroll
                for (int mt = 0; mt < 4; mt++) {
                    asm volatile(
                        "mma.sync.aligned.m16n8k8.row.col.f32.tf32.tf32.f32 "
                        "{%0,%1,%2,%3}, {%4,%5,%6,%7}, {%8,%9}, {%0,%1,%2,%3};"
                        : "+f"(acc[mt][nt][0]), "+f"(acc[mt][nt][1]),
                          "+f"(acc[mt][nt][2]), "+f"(acc[mt][nt][3])
                        : "r"(a[mt][0]), "r"(a[mt][1]), "r"(a[mt][2]), "r"(a[mt][3]),
                          "r"(b0), "r"(b1));
                }
            }
        }
        __syncthreads();
    }

    /* ---- epilogue: bias add (+ optional q-scale), direct global stores ---- */
    const bool do_scale = SCALE_Q && (n0 < DIMC);   /* q columns: first 384 of 1152 */
    #pragma unroll
    for (int mt = 0; mt < 4; mt++) {
        const int r0 = m0 + wm * 64 + mt * 16 + grp;
        #pragma unroll
        for (int nt = 0; nt < 8; nt++) {
            const int col = n0 + wn * 64 + nt * 8 + 2 * sub;
            const float2 bv = *reinterpret_cast<const float2*>(&bias[col]);
            float2 o0 = make_float2(acc[mt][nt][0] + bv.x, acc[mt][nt][1] + bv.y);
            float2 o1 = make_float2(acc[mt][nt][2] + bv.x, acc[mt][nt][3] + bv.y);
            if (do_scale) {
                o0.x *= QK_SCALE; o0.y *= QK_SCALE;
                o1.x *= QK_SCALE; o1.y *= QK_SCALE;
            }
            *reinterpret_cast<float2*>(&C[(size_t)r0 * N + col])       = o0;
            *reinterpret_cast<float2*>(&C[(size_t)(r0 + 8) * N + col]) = o1;
        }
    }
}

/* ============================================================================
 * tf32 pre-round (vectorized): dst = cvt.rna.tf32(src), fp32 container
 * ==========================================================================*/
__global__ void cvt_tf32(const float4* __restrict__ src, float4* __restrict__ dst, int n4)
{
    const int i = blockIdx.x * blockDim.x + threadIdx.x;
    if (i < n4) {
        float4 v = src[i];
        v.x = tf32r(v.x); v.y = tf32r(v.y); v.z = tf32r(v.z); v.w = tf32r(v.w);
        dst[i] = v;
    }
}

/* ============================================================================
 * Precompute gathered relative-position bias: g_bias[h][n*49+m]
 * ==========================================================================*/
__global__ void bias_gather(const float* __restrict__ bias_table,
                            const int* __restrict__ rel_index)
{
    const int h = blockIdx.x;
    for (int idx = threadIdx.x; idx < WIN_N * WIN_N; idx += blockDim.x)
        g_bias[h * WIN_N * WIN_N + idx] = bias_table[rel_index[idx] * NHEAD + h];
}

/* ============================================================================
 * Windowed attention: one block per (window b, head h). Same as the R6
 * passing version; ctx stores are tf32-rounded so the proj GEMM can
 * cp.async them raw.
 * ==========================================================================*/
#define QS 33
#define VS 36

__global__ void __launch_bounds__(128)
win_attn()
{
    __shared__ __align__(16) float qs[WIN_N * QS];
    __shared__ __align__(16) float ks[WIN_N * QS];
    __shared__ __align__(16) float vs[WIN_N * VS];
    __shared__ __align__(16) float ls[WIN_N * WIN_N];

    const int h = blockIdx.x;
    const int b = blockIdx.y;
    const int tid = threadIdx.x;

    const float* base = g_qkv + (size_t)b * WIN_N * QKV_N + h * HD;
    for (int idx = tid; idx < WIN_N * HD; idx += 128) {
        const int n = idx >> 5, d = idx & 31;
        const float* p = base + (size_t)n * QKV_N + d;
        qs[n * QS + d] = p[0];
        ks[n * QS + d] = p[DIMC];
        vs[n * VS + d] = p[2 * DIMC];
    }
    const float* bsrc = g_bias + h * WIN_N * WIN_N;
    for (int idx = tid; idx < WIN_N * WIN_N; idx += 128)
        ls[idx] = bsrc[idx];
    __syncthreads();

    for (int t = tid; t < 169; t += 128) {
        const int tn = t / 13, tm = t - tn * 13;
        const int nb = tn * 4, mb = tm * 4;
        const float* qp[4]; const float* kp[4];
        #pragma unroll
        for (int i = 0; i < 4; i++) {
            qp[i] = &qs[min(nb + i, WIN_N - 1) * QS];
            kp[i] = &ks[min(mb + i, WIN_N - 1) * QS];
        }
        float a[4][4] = {};
        #pragma unroll
        for (int d = 0; d < HD; d++) {
            float qv[4], kv[4];
            #pragma unroll
            for (int i = 0; i < 4; i++) qv[i] = qp[i][d];
            #pragma unroll
            for (int j = 0; j < 4; j++) kv[j] = kp[j][d];
            #pragma unroll
            for (int i = 0; i < 4; i++)
                #pragma unroll
                for (int j = 0; j < 4; j++) a[i][j] += qv[i] * kv[j];
        }
        #pragma unroll
        for (int i = 0; i < 4; i++) {
            if (nb + i >= WIN_N) break;
            #pragma unroll
            for (int j = 0; j < 4; j++)
                if (mb + j < WIN_N) ls[(nb + i) * WIN_N + mb + j] += a[i][j];
        }
    }
    __syncthreads();

    {
        const int warp = tid >> 5, lane = tid & 31;
        for (int n = warp; n < WIN_N; n += 4) {
            float* row = &ls[n * WIN_N];
            const bool has1 = (lane + 32) < WIN_N;
            float v0 = row[lane];
            float v1 = has1 ? row[lane + 32] : -3.402823e38f;
            float mx = fmaxf(v0, v1);
            #pragma unroll
            for (int off = 16; off >= 1; off >>= 1)
                mx = fmaxf(mx, __shfl_xor_sync(0xffffffffu, mx, off));
            float e0 = __expf(v0 - mx);
            float e1 = has1 ? __expf(v1 - mx) : 0.f;
            float s = e0 + e1;
            #pragma unroll
            for (int off = 16; off >= 1; off >>= 1)
                s += __shfl_xor_sync(0xffffffffu, s, off);
            const float inv = 1.f / s;
            row[lane] = e0 * inv;
            if (has1) row[lane + 32] = e1 * inv;
        }
    }
    __syncthreads();

    float* ctx = g_ctx + (size_t)b * WIN_N * DIMC + h * HD;
    for (int t = tid; t < 13 * 8; t += 128) {
        const int tn = t >> 3, td = t & 7;
        const int nb = tn * 4, d0 = td * 4;
        const float* pr[4];
        #pragma unroll
        for (int i = 0; i < 4; i++) pr[i] = &ls[min(nb + i, WIN_N - 1) * WIN_N];
        float a[4][4] = {};
        for (int m = 0; m < WIN_N; m++) {
            float4 vv = *reinterpret_cast<const float4*>(&vs[m * VS + d0]);
            float pv[4];
            #pragma unroll
            for (int i = 0; i < 4; i++) pv[i] = pr[i][m];
            #pragma unroll
            for (int i = 0; i < 4; i++) {
                a[i][0] += pv[i] * vv.x; a[i][1] += pv[i] * vv.y;
                a[i][2] += pv[i] * vv.z; a[i][3] += pv[i] * vv.w;
            }
        }
        #pragma unroll
        for (int i = 0; i < 4; i++) {
            if (nb + i >= WIN_N) break;
            float* o = ctx + (size_t)(nb + i) * DIMC + d0;
            o[0] = tf32r(a[i][0]); o[1] = tf32r(a[i][1]);
            o[2] = tf32r(a[i][2]); o[3] = tf32r(a[i][3]);
        }
    }
}

/* ============================================================================ */
extern "C" void kernel_launch(void* const* d_in, const int* in_sizes, int n_in,
                              void* d_out, int out_size)
{
    const float* x          = (const float*)d_in[0];
    const float* qkv_w      = (const float*)d_in[1];
    const float* qkv_b      = (const float*)d_in[2];
    const float* proj_w     = (const float*)d_in[3];
    const float* proj_b     = (const float*)d_in[4];
    const float* bias_table = (const float*)d_in[5];
    const int*   rel_index  = (const int*)d_in[6];
    float*       out        = (float*)d_out;

    float *qkv_ptr, *ctx_ptr, *xt_ptr, *wqt_ptr, *wpt_ptr;
    cudaGetSymbolAddress((void**)&qkv_ptr, g_qkv);
    cudaGetSymbolAddress((void**)&ctx_ptr, g_ctx);
    cudaGetSymbolAddress((void**)&xt_ptr,  g_xt);
    cudaGetSymbolAddress((void**)&wqt_ptr, g_wqt);
    cudaGetSymbolAddress((void**)&wpt_ptr, g_wpt);

    cudaFuncSetAttribute(gemm_mma<QKV_N, true>,  cudaFuncAttributeMaxDynamicSharedMemorySize, SMEM_DYN);
    cudaFuncSetAttribute(gemm_mma<DIMC, false>,  cudaFuncAttributeMaxDynamicSharedMemorySize, SMEM_DYN);

    /* 0) tf32 pre-round of all GEMM operands + bias gather (cheap) */
    {
        const int nx = MROWS * DIMC / 4;
        cvt_tf32<<<(nx + 255) / 256, 256>>>((const float4*)x, (float4*)xt_ptr, nx);
        const int nq = QKV_N * DIMC / 4;
        cvt_tf32<<<(nq + 255) / 256, 256>>>((const float4*)qkv_w, (float4*)wqt_ptr, nq);
        const int np = DIMC * DIMC / 4;
        cvt_tf32<<<(np + 255) / 256, 256>>>((const float4*)proj_w, (float4*)wpt_ptr, np);
        bias_gather<<<NHEAD, 256>>>(bias_table, rel_index);
    }

    /* 1) QKV = X * Wqkv^T + b (q pre-scaled), tf32 mma.sync */
    dim3 g1(QKV_N / 128, MROWS / 128);   /* (9, 1568) */
    gemm_mma<QKV_N, true><<<g1, 128, SMEM_DYN>>>(xt_ptr, wqt_ptr, qkv_b, qkv_ptr);

    /* 2) windowed attention (fp32) */
    dim3 g2(NHEAD, BWIN);                /* (12, 4096) */
    win_attn<<<g2, 128>>>();

    /* 3) OUT = CTX * Wproj^T + b, tf32 mma.sync */
    dim3 g3(DIMC / 128, MROWS / 128);    /* (3, 1568) */
    gemm_mma<DIMC, false><<<g3, 128, SMEM_DYN>>>(ctx_ptr, wpt_ptr, proj_b, out);
}